// round 7
// baseline (speedup 1.0000x reference)
#include <cuda_runtime.h>

// ExponentialGlobalConv: out[b,m,c] = DX * sum_n x[b,n] * exp(-|n-m|*DX/w_c) / (2 w_c)
// Uniform grid => separable exponential kernel => fwd+bwd IIR scan.
// R7: the CTA's whole 32-chunk window (4KB) is staged into smem with ONE
// coalesced float2 load per thread (zero-padded at row edges), and every
// chunk read is an LDS.128 broadcast instead of LDG.128 broadcast — this
// cuts the dominant LSU pipe load ~4x. Math identical to R6:
//   out[k] = fma(s, r^{k+1}, fma(u, r^{32-k}, fma(r, Floc[k-1], Bloc[k])))
// with seeds s,u = 8-term dot products over neighbor chunk end-sums (hop r^32).

#define NCH   32
#define NG    2048
#define NB    32
#define DXC   0.08f
#define CL    32
#define HALOC 8                  // halo chunks per side
#define OUTC  16                 // output chunks per block
#define WINCH (OUTC + 2*HALOC)   // 32 window chunks
#define NWARP 16
#define NTHREADS (NWARP * 32)
#define BPB   4

__global__ __launch_bounds__(NTHREADS, 1)
void egc_kernel(const float* __restrict__ x,
                const float* __restrict__ eta,
                float* __restrict__ out)
{
    __shared__ float xs[WINCH * CL];   // 4KB window: chunks base..base+31
    __shared__ float ef[24][32];       // fwd end-sums, window chunks 0..23
    __shared__ float eb[24][32];       // bwd end-sums, window chunks 8..31 (idx wc-8)

    const int tid  = threadIdx.x;
    const int lane = tid & 31;             // channel
    const int w    = tid >> 5;             // warp 0..15
    const int b    = blockIdx.x >> 2;      // batch row
    const int q    = blockIdx.x & 3;       // quarter

    // ---- stage window into smem: one float2 per thread, zero-padded ----
    {
        const float2* xrow2 = reinterpret_cast<const float2*>(x + (size_t)b * NG);
        const int i2 = (q * OUTC - HALOC) * (CL / 2) + tid;   // float2 index in row
        float2 v = make_float2(0.f, 0.f);
        if (i2 >= 0 && i2 < NG / 2) v = xrow2[i2];
        reinterpret_cast<float2*>(xs)[tid] = v;
    }

    // ---- per-channel params (under load shadow) ----
    const float e     = eta[lane];
    const float sig   = 1.0f / (1.0f + __expf(-e));
    const float wid   = 0.1f + 4.9f * sig;
    const float r     = __expf(-DXC / wid);
    const float scale = DXC / (2.0f * wid);
    const float r2 = r * r, r3 = r2 * r, r4 = r2 * r2;

    __syncthreads();

    // ---- own chunk (window 8+w) and halo chunk via LDS.128 broadcast ----
    float4 A[8], Bv[8];
    {
        const float4* pa = reinterpret_cast<const float4*>(xs + (HALOC + w) * CL);
        #pragma unroll
        for (int i = 0; i < 8; i++) A[i] = pa[i];
        const int h_wc = (w < HALOC) ? w : (w + 16);   // fwd halo 0..7 / bwd halo 24..31
        const float4* pb = reinterpret_cast<const float4*>(xs + h_wc * CL);
        #pragma unroll
        for (int i = 0; i < 8; i++) Bv[i] = pb[i];
    }

    float* ax = reinterpret_cast<float*>(A);
    const float* bx = reinterpret_cast<const float*>(Bv);

    // ---- pre-scale own chunk: everything downstream is scaled ----
    #pragma unroll
    for (int k = 0; k < CL; k++) ax[k] *= scale;

    // ---- loop1: own fwd chain + halo chain (2 independent chains) ----
    float Floc[CL];
    float F = 0.f, E = 0.f;
    if (w < HALOC) {
        #pragma unroll
        for (int k = 0; k < CL; k++) {
            F = fmaf(r, F, ax[k]); Floc[k] = F;
            E = fmaf(r, E, bx[k]);                 // fwd halo
        }
    } else {
        #pragma unroll
        for (int k = 0; k < CL; k++) {
            F = fmaf(r, F, ax[k]); Floc[k] = F;
            E = fmaf(r, E, bx[CL - 1 - k]);        // bwd halo
        }
    }
    E *= scale;                                    // zero-padded edges stay zero
    ef[HALOC + w][lane] = F;                       // own fwd end (scaled)
    if (w < HALOC) ef[w][lane] = E;                // fwd halo end (window w)
    else           eb[w + 8][lane] = E;            // bwd halo end (window w+16 -> idx w+8)

    // ---- loop2: own bwd chain, in place (Bloc[k] := ax[k]) ----
    {
        float Bw = 0.f;
        #pragma unroll
        for (int k = CL - 1; k >= 0; k--) {
            Bw = fmaf(r, Bw, ax[k]);
            ax[k] = Bw;
        }
        eb[w][lane] = Bw;                          // own bwd end (window 8+w -> idx w)
    }

    // ---- power tables (no cross-warp deps: before the barrier) ----
    float rp[CL];                                  // rp[k] = r^{k+1}
    rp[0] = r; rp[1] = r2; rp[2] = r3; rp[3] = r4;
    #pragma unroll
    for (int k = 4; k < CL; k++) rp[k] = rp[k - 4] * r4;
    const float rL = rp[31];                       // r^32
    float rLp[HALOC];                              // rL^d, d=0..7
    rLp[0] = 1.0f;
    #pragma unroll
    for (int d = 1; d < HALOC; d++) rLp[d] = rLp[d - 1] * rL;

    __syncthreads();

    // ---- seeds: 8-term dot products over neighbor end-sums ----
    float s = 0.f, u = 0.f;
    #pragma unroll
    for (int d = 1; d <= HALOC; d++) {
        s = fmaf(ef[HALOC + w - d][lane], rLp[d - 1], s);
        u = fmaf(eb[w + d][lane],         rLp[d - 1], u);
    }

    // ---- combine + store: 3 independent FMAs per element ----
    float* op = out + ((size_t)b * NG + (size_t)(q * OUTC + w) * CL) * NCH + lane;
    op[0] = fmaf(s, rp[0], fmaf(u, rp[31], ax[0]));
    #pragma unroll
    for (int k = 1; k < CL; k++) {
        const float t = fmaf(r, Floc[k - 1], ax[k]);
        op[(size_t)k * NCH] = fmaf(s, rp[k], fmaf(u, rp[31 - k], t));
    }
}

extern "C" void kernel_launch(void* const* d_in, const int* in_sizes, int n_in,
                              void* d_out, int out_size)
{
    const float* x   = (const float*)d_in[0];  // inputs (32, 2048)
    // d_in[1] = grids (unused: uniform grid, spacing DX by construction)
    const float* eta = (const float*)d_in[2];  // eta (32,)
    float* out = (float*)d_out;                // (32, 2048, 32) fp32

    egc_kernel<<<NB * BPB, NTHREADS>>>(x, eta, out);
}

// round 8
// speedup vs baseline: 1.0332x; 1.0332x over previous
#include <cuda_runtime.h>

// ExponentialGlobalConv: out[b,m,c] = DX * sum_n x[b,n] * exp(-|n-m|*DX/w_c) / (2 w_c)
// Uniform grid => separable exponential kernel => fwd+bwd IIR scan.
// R8: occupancy push. 256 CTAs (OUTC=8 chunks/CTA), every warp runs exactly
// two 32-deep chains:
//   warps 0-7 : own chunk fwd (Floc) + bwd (Bloc in place) -> combine+store
//   warps 8-11: two fwd-halo end-only scans (window chunks 0..7)
//   warps 12-15: two bwd-halo end-only scans (window chunks 16..23)
// Seeds s,u = 8-term dot products over neighbor chunk end-sums (hop r^32).
//   out[k] = fma(s, r^{k+1}, fma(u, r^{32-k}, fma(r, Floc[k-1], Bloc[k])))

#define NCH   32
#define NG    2048
#define NB    32
#define DXC   0.08f
#define CL    32
#define HALOC 8                  // halo chunks per side
#define OUTC  8                  // output chunks per block
#define NWARP 16
#define NTHREADS (NWARP * 32)
#define BPB   8                  // blocks per batch row
#define NGC   (NG / CL)          // 64 global chunks per row

__global__ __launch_bounds__(NTHREADS, 1)
void egc_kernel(const float* __restrict__ x,
                const float* __restrict__ eta,
                float* __restrict__ out)
{
    __shared__ float ef[16][32];   // fwd end-sums, window chunks 0..15
    __shared__ float eb[16][32];   // bwd end-sums, window chunks 8..23 (idx wc-8)

    const int tid  = threadIdx.x;
    const int lane = tid & 31;             // channel
    const int w    = tid >> 5;             // warp 0..15
    const int b    = blockIdx.x >> 3;      // batch row
    const int q    = blockIdx.x & 7;       // eighth of the grid dim
    const float* xrow = x + (size_t)b * NG;
    const int baseg = q * OUTC - HALOC;    // global chunk at window wc=0

    // ---- per-channel params ----
    const float e     = eta[lane];
    const float sig   = 1.0f / (1.0f + __expf(-e));
    const float wid   = 0.1f + 4.9f * sig;
    const float r     = __expf(-DXC / wid);
    const float scale = DXC / (2.0f * wid);
    const float r2 = r * r, r3 = r2 * r, r4 = r2 * r2;

    float ax[CL], Floc[CL];
    float rp[CL];                          // rp[k] = r^{k+1} (own warps only)

    if (w < OUTC) {
        // ================== own chunk (window 8+w, global q*8+w) ==================
        {
            const float4* pa = reinterpret_cast<const float4*>(xrow + (size_t)(q * OUTC + w) * CL);
            #pragma unroll
            for (int i = 0; i < 8; i++) reinterpret_cast<float4*>(ax)[i] = pa[i];
        }
        #pragma unroll
        for (int k = 0; k < CL; k++) ax[k] *= scale;   // pre-scale

        // fwd chain (keep Floc)
        float F = 0.f;
        #pragma unroll
        for (int k = 0; k < CL; k++) { F = fmaf(r, F, ax[k]); Floc[k] = F; }
        ef[HALOC + w][lane] = F;

        // bwd chain, in place (Bloc[k] := ax[k])
        float Bw = 0.f;
        #pragma unroll
        for (int k = CL - 1; k >= 0; k--) { Bw = fmaf(r, Bw, ax[k]); ax[k] = Bw; }
        eb[w][lane] = Bw;                              // idx = (8+w)-8

        // power table rp[k] = r^{k+1}
        rp[0] = r; rp[1] = r2; rp[2] = r3; rp[3] = r4;
        #pragma unroll
        for (int k = 4; k < CL; k++) rp[k] = rp[k - 4] * r4;
    } else if (w < 12) {
        // ============ fwd halo: window chunks 2j, 2j+1 (j = w-8) ============
        const int j = w - 8;
        const int g0 = baseg + 2 * j, g1 = g0 + 1;
        const bool ok0 = (g0 >= 0), ok1 = (g1 >= 0);   // left edge only
        float4 V0[8], V1[8];
        {
            const float4* p0 = reinterpret_cast<const float4*>(xrow + (size_t)(ok0 ? g0 : 0) * CL);
            const float4* p1 = reinterpret_cast<const float4*>(xrow + (size_t)(ok1 ? g1 : 0) * CL);
            #pragma unroll
            for (int i = 0; i < 8; i++) { V0[i] = p0[i]; V1[i] = p1[i]; }
        }
        const float* b0 = reinterpret_cast<const float*>(V0);
        const float* b1 = reinterpret_cast<const float*>(V1);
        float E0 = 0.f, E1 = 0.f;
        #pragma unroll
        for (int k = 0; k < CL; k++) {                 // two interleaved chains
            E0 = fmaf(r, E0, b0[k]);
            E1 = fmaf(r, E1, b1[k]);
        }
        ef[2 * j][lane]     = ok0 ? E0 * scale : 0.f;
        ef[2 * j + 1][lane] = ok1 ? E1 * scale : 0.f;
    } else {
        // ============ bwd halo: window chunks 16+2j, 17+2j (j = w-12) ============
        const int j = w - 12;
        const int g0 = baseg + 16 + 2 * j, g1 = g0 + 1;
        const bool ok0 = (g0 < NGC), ok1 = (g1 < NGC); // right edge only
        float4 V0[8], V1[8];
        {
            const float4* p0 = reinterpret_cast<const float4*>(xrow + (size_t)(ok0 ? g0 : 0) * CL);
            const float4* p1 = reinterpret_cast<const float4*>(xrow + (size_t)(ok1 ? g1 : 0) * CL);
            #pragma unroll
            for (int i = 0; i < 8; i++) { V0[i] = p0[i]; V1[i] = p1[i]; }
        }
        const float* b0 = reinterpret_cast<const float*>(V0);
        const float* b1 = reinterpret_cast<const float*>(V1);
        float E0 = 0.f, E1 = 0.f;
        #pragma unroll
        for (int k = CL - 1; k >= 0; k--) {            // two interleaved chains
            E0 = fmaf(r, E0, b0[k]);
            E1 = fmaf(r, E1, b1[k]);
        }
        eb[8 + 2 * j][lane] = ok0 ? E0 * scale : 0.f;  // wc 16+2j -> idx 8+2j
        eb[9 + 2 * j][lane] = ok1 ? E1 * scale : 0.f;
    }

    __syncthreads();

    if (w < OUTC) {
        // ---- seeds: 8-term dot products over neighbor end-sums ----
        const float rL = rp[31];                       // r^32
        float rLd = 1.0f;
        float s = 0.f, u = 0.f;
        #pragma unroll
        for (int d = 1; d <= HALOC; d++) {
            s = fmaf(ef[HALOC + w - d][lane], rLd, s);
            u = fmaf(eb[w + d][lane],         rLd, u);
            rLd *= rL;
        }

        // ---- combine + store: 3 independent FMAs per element ----
        float* op = out + ((size_t)b * NG + (size_t)(q * OUTC + w) * CL) * NCH + lane;
        op[0] = fmaf(s, rp[0], fmaf(u, rp[31], ax[0]));
        #pragma unroll
        for (int k = 1; k < CL; k++) {
            const float t = fmaf(r, Floc[k - 1], ax[k]);
            op[(size_t)k * NCH] = fmaf(s, rp[k], fmaf(u, rp[31 - k], t));
        }
    }
}

extern "C" void kernel_launch(void* const* d_in, const int* in_sizes, int n_in,
                              void* d_out, int out_size)
{
    const float* x   = (const float*)d_in[0];  // inputs (32, 2048)
    // d_in[1] = grids (unused: uniform grid, spacing DX by construction)
    const float* eta = (const float*)d_in[2];  // eta (32,)
    float* out = (float*)d_out;                // (32, 2048, 32) fp32

    egc_kernel<<<NB * BPB, NTHREADS>>>(x, eta, out);
}

// round 9
// speedup vs baseline: 1.0728x; 1.0383x over previous
#include <cuda_runtime.h>

// ExponentialGlobalConv: out[b,m,c] = DX * sum_n x[b,n] * exp(-|n-m|*DX/w_c) / (2 w_c)
// Uniform grid => separable exponential kernel => fwd+bwd IIR scan.
// R9: occupancy fix. 256-thread CTAs (8 warps), OUTC=8, grid=256 -> regs<=128
// gives 2 resident CTAs/SM in a single wave (R8's 512-thread CTAs were pinned
// to 1 CTA/SM by the register file; its 256 CTAs ran as 2 serialized waves).
// Uniform warp roles: each warp scans its own chunk (fwd keeping Floc, bwd in
// place) and fuses one fwd-halo and one bwd-halo end-scan (scalar LDS
// broadcasts from a 3KB staged, zero-padded window). Seeds = 8-term dot
// products over neighbor end-sums (hop r^32); combine is 3 FMAs/element:
//   out[k] = fma(s, r^{k+1}, fma(u, r^{32-k}, fma(r, Floc[k-1], Bloc[k])))

#define NCH   32
#define NG    2048
#define NB    32
#define DXC   0.08f
#define CL    32
#define HALOC 8                   // halo chunks per side
#define OUTC  8                   // output chunks per block
#define WINCH (OUTC + 2*HALOC)    // 24 window chunks
#define NWARP 8
#define NTHREADS (NWARP * 32)     // 256
#define BPB   8                   // blocks per batch row

__global__ __launch_bounds__(NTHREADS, 2)
void egc_kernel(const float* __restrict__ x,
                const float* __restrict__ eta,
                float* __restrict__ out)
{
    __shared__ float xs[WINCH * CL];   // 3KB zero-padded window, chunks baseg..baseg+23
    __shared__ float ef[16][32];       // fwd end-sums, window chunks 0..15
    __shared__ float eb[16][32];       // bwd end-sums, window chunks 8..23 (idx wc-8)

    const int tid  = threadIdx.x;
    const int lane = tid & 31;              // channel
    const int w    = tid >> 5;              // warp 0..7
    const int b    = blockIdx.x >> 3;       // batch row
    const int q    = blockIdx.x & 7;        // eighth of grid dim
    const int baseg = q * OUTC - HALOC;     // global chunk at window wc=0

    // ---- stage window into smem: threads 0..191 load one float4, zero-padded ----
    if (tid < WINCH * CL / 4) {
        const float4* xrow4 = reinterpret_cast<const float4*>(x + (size_t)b * NG);
        const int g4 = baseg * (CL / 4) + tid;          // global float4 index
        float4 v = make_float4(0.f, 0.f, 0.f, 0.f);
        if (g4 >= 0 && g4 < NG / 4) v = xrow4[g4];
        reinterpret_cast<float4*>(xs)[tid] = v;
    }

    // ---- per-channel params (under load shadow) ----
    const float e     = eta[lane];
    const float sig   = 1.0f / (1.0f + __expf(-e));
    const float wid   = 0.1f + 4.9f * sig;
    const float r     = __expf(-DXC / wid);
    const float scale = DXC / (2.0f * wid);
    const float r2 = r * r, r3 = r2 * r, r4 = r2 * r2;

    // power table rp[k] = r^{k+1} (no cross-warp deps)
    float rp[CL];
    rp[0] = r; rp[1] = r2; rp[2] = r3; rp[3] = r4;
    #pragma unroll
    for (int k = 4; k < CL; k++) rp[k] = rp[k - 4] * r4;
    const float rL = rp[31];                 // r^32

    __syncthreads();

    // ---- own chunk (window 8+w) into regs, pre-scaled ----
    float ax[CL];
    {
        const float4* pa = reinterpret_cast<const float4*>(xs + (HALOC + w) * CL);
        #pragma unroll
        for (int i = 0; i < 8; i++) reinterpret_cast<float4*>(ax)[i] = pa[i];
    }
    #pragma unroll
    for (int k = 0; k < CL; k++) ax[k] *= scale;

    // ---- pass 1: own fwd chain (keep Floc) + fwd-halo end-scan (window chunk w) ----
    float Floc[CL];
    {
        const float* hx = xs + w * CL;
        float F = 0.f, E = 0.f;
        #pragma unroll
        for (int k = 0; k < CL; k++) {
            F = fmaf(r, F, ax[k]); Floc[k] = F;
            E = fmaf(r, E, hx[k]);               // scalar LDS broadcast
        }
        ef[HALOC + w][lane] = F;                 // own fwd end (scaled)
        ef[w][lane] = E * scale;                 // fwd halo end
    }

    // ---- pass 2: own bwd chain in place (Bloc := ax) + bwd-halo end-scan (wc 16+w) ----
    {
        const float* hx = xs + (16 + w) * CL;
        float Bw = 0.f, E = 0.f;
        #pragma unroll
        for (int k = CL - 1; k >= 0; k--) {
            Bw = fmaf(r, Bw, ax[k]); ax[k] = Bw;
            E = fmaf(r, E, hx[k]);
        }
        eb[w][lane] = Bw;                        // own bwd end (wc 8+w -> idx w)
        eb[8 + w][lane] = E * scale;             // bwd halo end (wc 16+w -> idx 8+w)
    }

    __syncthreads();

    // ---- seeds: 8-term dot products over neighbor end-sums ----
    float s = 0.f, u = 0.f;
    {
        float rLd = 1.0f;
        #pragma unroll
        for (int d = 1; d <= HALOC; d++) {
            s = fmaf(ef[HALOC + w - d][lane], rLd, s);
            u = fmaf(eb[w + d][lane],         rLd, u);
            rLd *= rL;
        }
    }

    // ---- combine + store: 3 independent FMAs per element ----
    float* op = out + ((size_t)b * NG + (size_t)(q * OUTC + w) * CL) * NCH + lane;
    op[0] = fmaf(s, rp[0], fmaf(u, rp[31], ax[0]));
    #pragma unroll
    for (int k = 1; k < CL; k++) {
        const float t = fmaf(r, Floc[k - 1], ax[k]);
        op[(size_t)k * NCH] = fmaf(s, rp[k], fmaf(u, rp[31 - k], t));
    }
}

extern "C" void kernel_launch(void* const* d_in, const int* in_sizes, int n_in,
                              void* d_out, int out_size)
{
    const float* x   = (const float*)d_in[0];  // inputs (32, 2048)
    // d_in[1] = grids (unused: uniform grid, spacing DX by construction)
    const float* eta = (const float*)d_in[2];  // eta (32,)
    float* out = (float*)d_out;                // (32, 2048, 32) fp32

    egc_kernel<<<NB * BPB, NTHREADS>>>(x, eta, out);
}